// round 17
// baseline (speedup 1.0000x reference)
#include <cuda_runtime.h>
#include <cstdint>

// RVQ — mma.sync tf32 approx GEMM + exact-fp32 refine.
// R16 core (cells + one barrier/chunk, frozen threshold semantics) with
// conflict-free LDS.64 fragment loads: pitch 136 + e-pair permutation.
// embeddings: [16, 128, 64, 64] f32 (d_in[0])
// codebooks : [8, 1024, 128]  f32  (d_in[1])
// out       : [16, 128, 64, 64] f32

#define NBOOK   8
#define KCB     1024
#define EDIM    128
#define NROWS   65536
#define TPB     512
#define CHUNK   128
#define NCHUNK  (KCB / CHUNK)
#define EPSM    1e-3f
#define CANDMAX 16
#define PA      136   // 136 mod 32 == 8 -> conflict-free paired LDS.64
#define PB      136

// float-index smem offsets
#define OFF_A     0
#define OFF_B0    (OFF_A + 128 * PA)       // also: final quant tile
#define OFF_B1    (OFF_B0 + CHUNK * PB)    // also: transpose scratch
#define OFF_NORM  (OFF_B1 + CHUNK * PB)
#define OFF_SA    (OFF_NORM + KCB)
#define OFF_CELLS (OFF_SA + 128)           // [NCHUNK][128] per-chunk min cells
#define OFF_CNT   (OFF_CELLS + NCHUNK * 128)
#define OFF_BEST8 (OFF_CNT + 128)          // [8][128] ints
#define OFF_CAND  (OFF_BEST8 + NBOOK * 128)
#define SM_FLOATS (OFF_CAND + 128 * CANDMAX)   // 57600 floats = 230400 B

__device__ float g_norms[NBOOK * KCB];
__device__ __align__(16) float g_cbperm[NBOOK * KCB * EDIM];

// e-pair permutation within each 8-group: orig j -> 2*(j&3) + (j>>2).
// Puts orig (j, j+4) at adjacent slots (2j, 2j+1) => one LDS.64 per pair.
__host__ __device__ __forceinline__ int eperm(int e) {
    return (e & ~7) | (((e & 3) << 1) | ((e >> 2) & 1));
}

__device__ __forceinline__ uint32_t smem_u32(const void* p) {
    uint32_t a;
    asm("{ .reg .u64 t; cvta.to.shared.u64 t, %1; cvt.u32.u64 %0, t; }"
        : "=r"(a) : "l"(p));
    return a;
}
__device__ __forceinline__ void cp_async16(uint32_t dst, const void* src) {
    asm volatile("cp.async.cg.shared.global [%0], [%1], 16;"
                 :: "r"(dst), "l"(src) : "memory");
}
#define MMA_TF32(d, a, b0, b1)                                          \
    asm volatile(                                                        \
        "mma.sync.aligned.m16n8k8.row.col.f32.tf32.tf32.f32 "           \
        "{%0,%1,%2,%3}, {%4,%5,%6,%7}, {%8,%9}, {%0,%1,%2,%3};"         \
        : "+f"((d)[0]), "+f"((d)[1]), "+f"((d)[2]), "+f"((d)[3])         \
        : "r"((a)[0]), "r"((a)[1]), "r"((a)[2]), "r"((a)[3]),            \
          "r"(b0), "r"(b1))

// ---------------------------------------------------------------------------
// norms: C_k = sum_e fl(c*c), e ascending (exact chain); float4 loads
// ---------------------------------------------------------------------------
__global__ void k_norms(const float* __restrict__ cb) {
    int idx = blockIdx.x * 64 + threadIdx.x;
    if (idx >= NBOOK * KCB) return;
    const float4* c4 = (const float4*)(cb + (size_t)idx * EDIM);
    float acc = 0.0f;
#pragma unroll 8
    for (int e = 0; e < EDIM / 4; e++) {
        float4 v = __ldg(c4 + e);
        acc = __fadd_rn(acc, __fmul_rn(v.x, v.x));
        acc = __fadd_rn(acc, __fmul_rn(v.y, v.y));
        acc = __fadd_rn(acc, __fmul_rn(v.z, v.z));
        acc = __fadd_rn(acc, __fmul_rn(v.w, v.w));
    }
    g_norms[idx] = acc;
}

// ---------------------------------------------------------------------------
// prep: e-permuted codebook copy (contiguous cp.async for paired fragments)
// ---------------------------------------------------------------------------
__global__ void k_perm(const float* __restrict__ cb) {
    int idx = blockIdx.x * blockDim.x + threadIdx.x;
    if (idx >= NBOOK * KCB * EDIM) return;
    g_cbperm[(idx & ~(EDIM - 1)) | eperm(idx & (EDIM - 1))] = cb[idx];
}

// ---------------------------------------------------------------------------
// fused RVQ: one CTA = 128 rows through all 8 books. 512 threads (16 warps).
// Warp grid 4M x 4N; warp tile 32 rows x 32 codes. A/B smem e-pair-permuted.
// ---------------------------------------------------------------------------
__global__ void __launch_bounds__(TPB, 1)
k_rvq(const float* __restrict__ emb, const float* __restrict__ cb,
      float* __restrict__ out) {
    extern __shared__ float smf[];
    const uint32_t sb = smem_u32(smf);
    const int t = threadIdx.x, lane = t & 31, w = t >> 5;
    const int wm = w & 3, wn = w >> 2;     // 4 M-warps x 4 N-warps
    const int blk = blockIdx.x;
    const int b = blk >> 5;                // batch
    const int hw0 = (blk & 31) << 7;       // hw offset

    float* A     = smf + OFF_A;            // e-pair-permuted residual tile
    float* sNorm = smf + OFF_NORM;
    float* sA    = smf + OFF_SA;
    unsigned* cellsU = (unsigned*)(smf + OFF_CELLS);
    int*   cnt    = (int*)(smf + OFF_CNT);
    int*   sBest8 = (int*)(smf + OFF_BEST8);
    int*   candk  = (int*)(smf + OFF_CAND);

    // load residual tile (exact values, permuted slots)
    for (int v = t; v < 128 * 128; v += TPB) {
        int e = v >> 7, i = v & 127;
        A[i * PA + eperm(e)] = emb[((size_t)(b * 128 + e) << 12) + hw0 + i];
    }
    __syncthreads();

    const int frow = lane >> 2;            // 0..7
    const int fcol = lane & 3;             // 0..3

    for (int book = 0; book < NBOOK; book++) {
        const float* cbg  = cb + (size_t)book * KCB * EDIM;       // original
        const float* cbp  = g_cbperm + (size_t)book * KCB * EDIM; // permuted

        // book-start: norms, reset cells/cnt, exact A-norms
        for (int v = t; v < KCB; v += TPB) sNorm[v] = g_norms[book * KCB + v];
        for (int v = t; v < NCHUNK * 128; v += TPB) cellsU[v] = 0x7f7fffffu;
        if (t < 128) {
            cnt[t] = 0;
            // A = ||r||^2 exact chain (ORIGINAL e ascending)
            float acc = 0.0f;
            const float* ar = &A[t * PA];
            for (int e8 = 0; e8 < EDIM; e8 += 8) {
#pragma unroll
                for (int j = 0; j < 4; j++) {   // orig e8+0..3 at slots 0,2,4,6
                    float v = ar[e8 + 2 * j];
                    acc = __fadd_rn(acc, __fmul_rn(v, v));
                }
#pragma unroll
                for (int j = 0; j < 4; j++) {   // orig e8+4..7 at slots 1,3,5,7
                    float v = ar[e8 + 2 * j + 1];
                    acc = __fadd_rn(acc, __fmul_rn(v, v));
                }
            }
            sA[t] = acc;
        }
        __syncthreads();

        float arg[2][2], premin[2][2];
#pragma unroll
        for (int mt = 0; mt < 2; mt++)
#pragma unroll
            for (int h = 0; h < 2; h++) {
                arg[mt][h] = sA[wm * 32 + mt * 16 + frow + h * 8];
                premin[mt][h] = 3.4e38f;
            }

        // prologue: stage chunk 0 (permuted source) into B0
        for (int v = t; v < CHUNK * 32; v += TPB) {
            int code = v >> 5, s = v & 31;
            cp_async16(sb + (OFF_B0 + code * PB + s * 4) * 4,
                       cbp + (size_t)code * EDIM + s * 4);
        }
        asm volatile("cp.async.commit_group;" ::: "memory");
        asm volatile("cp.async.wait_group 0;" ::: "memory");
        __syncthreads();

        for (int c = 0; c < NCHUNK; c++) {
            const float* Bc = smf + ((c & 1) ? OFF_B1 : OFF_B0);

            // prefetch next chunk (permuted source) into the other buffer
            if (c + 1 < NCHUNK) {
                int nboff = ((c + 1) & 1) ? OFF_B1 : OFF_B0;
                const float* srcn = cbp + (size_t)(c + 1) * CHUNK * EDIM;
                for (int v = t; v < CHUNK * 32; v += TPB) {
                    int code = v >> 5, s = v & 31;
                    cp_async16(sb + (nboff + code * PB + s * 4) * 4,
                               srcn + (size_t)code * EDIM + s * 4);
                }
                asm volatile("cp.async.commit_group;" ::: "memory");
            }

            // ---- tf32 MMA: paired LDS.64 fragments (conflict-free @136) ----
            float d[2][4][4];
#pragma unroll
            for (int mt = 0; mt < 2; mt++)
#pragma unroll
                for (int nt = 0; nt < 4; nt++)
#pragma unroll
                    for (int q = 0; q < 4; q++) d[mt][nt][q] = 0.0f;

#pragma unroll 4
            for (int ks = 0; ks < 16; ks++) {
                int k0 = ks * 8;
                uint32_t a[2][4];
#pragma unroll
                for (int mt = 0; mt < 2; mt++) {
                    int r0 = wm * 32 + mt * 16 + frow;
                    uint2 lo = *(const uint2*)&A[r0 * PA + k0 + 2 * fcol];
                    uint2 hi = *(const uint2*)&A[(r0 + 8) * PA + k0 + 2 * fcol];
                    a[mt][0] = lo.x; a[mt][1] = hi.x;   // orig k0+fcol
                    a[mt][2] = lo.y; a[mt][3] = hi.y;   // orig k0+fcol+4
                }
#pragma unroll
                for (int nt = 0; nt < 4; nt++) {
                    int cl = wn * 32 + nt * 8 + frow;
                    uint2 bv = *(const uint2*)&Bc[cl * PB + k0 + 2 * fcol];
                    MMA_TF32(d[0][nt], a[0], bv.x, bv.y);
                    MMA_TF32(d[1][nt], a[1], bv.x, bv.y);
                }
            }

            // ---- epilogue: d_app = fma(-2,S,A) + C ----
            int kchunk = c * CHUNK + wn * 32;
#pragma unroll
            for (int mt = 0; mt < 2; mt++)
#pragma unroll
                for (int nt = 0; nt < 4; nt++)
#pragma unroll
                    for (int q = 0; q < 4; q++) {
                        int k = kchunk + nt * 8 + 2 * fcol + (q & 1);
                        d[mt][nt][q] = __fadd_rn(
                            __fmaf_rn(-2.0f, d[mt][nt][q], arg[mt][q >> 1]),
                            sNorm[k]);
                    }

            // per-chunk min into cells[c] ONLY (no race with collect(c))
#pragma unroll
            for (int mt = 0; mt < 2; mt++)
#pragma unroll
                for (int h = 0; h < 2; h++) {
                    float lm = 3.4e38f;
#pragma unroll
                    for (int nt = 0; nt < 4; nt++)
                        lm = fminf(lm, fminf(d[mt][nt][h * 2],
                                             d[mt][nt][h * 2 + 1]));
                    int row = wm * 32 + mt * 16 + frow + h * 8;
                    atomicMin(&cellsU[c * 128 + row], __float_as_uint(lm));
                }

            asm volatile("cp.async.wait_group 0;" ::: "memory");
            __syncthreads();   // seals cells[c]; publishes next B buffer

            // ---- collect(c): full prefix-min through chunk c + EPSM ----
#pragma unroll
            for (int mt = 0; mt < 2; mt++)
#pragma unroll
                for (int h = 0; h < 2; h++) {
                    int row = wm * 32 + mt * 16 + frow + h * 8;
                    float pm = fminf(premin[mt][h],
                                     __uint_as_float(cellsU[c * 128 + row]));
                    premin[mt][h] = pm;
                    float thr = pm + EPSM;
#pragma unroll
                    for (int nt = 0; nt < 4; nt++)
#pragma unroll
                        for (int qq = 0; qq < 2; qq++) {
                            if (d[mt][nt][h * 2 + qq] <= thr) {
                                int k = kchunk + nt * 8 + 2 * fcol + qq;
                                int p = atomicAdd(&cnt[row], 1);
                                if (p < CANDMAX)
                                    candk[row * CANDMAX + p] = k;
                            }
                        }
                }
        }
        __syncthreads();   // all collects done before refine reads cnt/candk

        // ---- exact refine: thread t owns row t (ORIGINAL e-order chains) ----
        if (t < 128) {
            int n = cnt[t];
            float Arow = sA[t];
            float bd = 3.4e38f; int bk = 0x7fffffff;
            const float* ar = &A[t * PA];
            if (n <= CANDMAX) {
                for (int i = 0; i < n; i++) {
                    int k = candk[t * CANDMAX + i];
                    const float* cp = cbg + (size_t)k * EDIM;
                    float dot = 0.0f;
#pragma unroll 8
                    for (int e = 0; e < EDIM; e += 4) {
                        float4 c4 = __ldg((const float4*)(cp + e));
                        int pb = (e & ~7) | ((e & 4) >> 2);  // slot of orig e
                        dot = __fmaf_rn(ar[pb],     c4.x, dot);
                        dot = __fmaf_rn(ar[pb + 2], c4.y, dot);
                        dot = __fmaf_rn(ar[pb + 4], c4.z, dot);
                        dot = __fmaf_rn(ar[pb + 6], c4.w, dot);
                    }
                    float dd = __fadd_rn(__fsub_rn(Arow, 2.0f * dot), sNorm[k]);
                    if (dd < bd || (dd == bd && k < bk)) { bd = dd; bk = k; }
                }
            } else {   // safety fallback: exact full scan (deterministic)
                for (int k = 0; k < KCB; k++) {
                    const float* cp = cbg + (size_t)k * EDIM;
                    float dot = 0.0f;
                    for (int e = 0; e < EDIM; e += 4) {
                        float4 c4 = __ldg((const float4*)(cp + e));
                        int pb = (e & ~7) | ((e & 4) >> 2);
                        dot = __fmaf_rn(ar[pb],     c4.x, dot);
                        dot = __fmaf_rn(ar[pb + 2], c4.y, dot);
                        dot = __fmaf_rn(ar[pb + 4], c4.z, dot);
                        dot = __fmaf_rn(ar[pb + 6], c4.w, dot);
                    }
                    float dd = __fadd_rn(__fsub_rn(Arow, 2.0f * dot), sNorm[k]);
                    if (dd < bd) { bd = dd; bk = k; }
                }
            }
            sBest8[book * 128 + t] = bk;
        }
        __syncthreads();

        // ---- res -= dec (SMEM, exact, permuted slots). Skip last book. ----
        if (book < NBOOK - 1) {
            for (int v = t; v < 128 * 32; v += TPB) {
                int row = v >> 5, e4 = (v & 31) << 2;    // orig e group
                int k = sBest8[book * 128 + row];
                float4 dec = __ldg((const float4*)(cbg + (size_t)k * EDIM + e4));
                float* rp = &A[row * PA];
                int pb = (e4 & ~7) | ((e4 & 4) >> 2);
                rp[pb]     = __fsub_rn(rp[pb],     dec.x);
                rp[pb + 2] = __fsub_rn(rp[pb + 2], dec.y);
                rp[pb + 4] = __fsub_rn(rp[pb + 4], dec.z);
                rp[pb + 6] = __fsub_rn(rp[pb + 6], dec.w);
            }
            __syncthreads();
        }
    }
    __syncthreads();

    // ---- quant reconstruction: q = ((dec0+dec1)+...+dec7), exact order ----
    // Q in dead B0 region, ORIGINAL e-order, pitch PA.
    float* Q = smf + OFF_B0;
    for (int v = t; v < 128 * 32; v += TPB) {
        int row = v >> 5, e4 = (v & 31) << 2;
        float4 q = __ldg((const float4*)(
            cb + ((size_t)sBest8[row]) * EDIM + e4));   // book 0
#pragma unroll
        for (int bkk = 1; bkk < NBOOK; bkk++) {
            int k = sBest8[bkk * 128 + row];
            float4 dv = __ldg((const float4*)(
                cb + ((size_t)bkk * KCB + k) * EDIM + e4));
            q.x = __fadd_rn(q.x, dv.x); q.y = __fadd_rn(q.y, dv.y);
            q.z = __fadd_rn(q.z, dv.z); q.w = __fadd_rn(q.w, dv.w);
        }
        *(float4*)&Q[row * PA + e4] = q;
    }
    __syncthreads();

    // ---- output: Q [row][e] (smem) -> out NCHW, warp-tiled transpose ----
    {
        float* ts = smf + OFF_B1 + w * (32 * 33);
        int i0 = (w & 3) * 32, e0 = (w >> 2) * 32;
#pragma unroll 4
        for (int r = 0; r < 32; r++)
            ts[r * 33 + lane] = Q[(i0 + r) * PA + e0 + lane];
        __syncwarp();
#pragma unroll 4
        for (int r = 0; r < 32; r++)
            out[((size_t)(b * 128 + e0 + r) << 12) + hw0 + i0 + lane] =
                ts[lane * 33 + r];
    }
}

// ---------------------------------------------------------------------------
extern "C" void kernel_launch(void* const* d_in, const int* in_sizes, int n_in,
                              void* d_out, int out_size) {
    (void)in_sizes; (void)n_in; (void)out_size;
    const float* emb = (const float*)d_in[0];
    const float* cb  = (const float*)d_in[1];
    float* out = (float*)d_out;

    const int smem_bytes = SM_FLOATS * 4;
    cudaFuncSetAttribute(k_rvq, cudaFuncAttributeMaxDynamicSharedMemorySize,
                         smem_bytes);
    k_norms<<<NBOOK * KCB / 64, 64>>>(cb);
    k_perm<<<(NBOOK * KCB * EDIM + 255) / 256, 256>>>(cb);
    k_rvq<<<NROWS / 128, TPB, smem_bytes>>>(emb, cb, out);
}